// round 17
// baseline (speedup 1.0000x reference)
#include <cuda_runtime.h>
#include <cuda_bf16.h>
#include <cstdint>

#define N_NODES 50000
#define EMB 128
#define N_EDGES 600000
#define NLAYER 5
#define BN_EPS 1e-5f

// ---------------- device scratch ----------------
__device__ float    g_h[N_NODES * EMB];            // node features fp32
__device__ uint32_t g_aggp[N_NODES * EMB];         // agg packed hi/lo bf16
__device__ uint32_t g_hiddenp[N_NODES * 2 * EMB];  // hidden packed hi/lo bf16
__device__ float    g_h2[N_NODES * EMB];           // MLP out pre-BN fp32
__device__ float    g_sums[2 * EMB];
__device__ float    g_scale[EMB];
__device__ float    g_shift[EMB];
__device__ int      g_counts[N_NODES];
__device__ int      g_cursor[N_NODES];
__device__ int      g_rowptr[N_NODES + 1];
__device__ unsigned g_elist[N_EDGES];
__device__ uint32_t g_w1p[NLAYER * 256 * 128];     // W1 transposed+packed [l][n][k]
__device__ uint32_t g_w2p[NLAYER * 128 * 256];     // W2 transposed+packed [l][n][k]

// ---------------- helpers ----------------
__device__ __forceinline__ uint32_t packhilo(float v) {
    __nv_bfloat16 h = __float2bfloat16(v);
    float hf = __bfloat162float(h);
    __nv_bfloat16 lo = __float2bfloat16(v - hf);
    return ((uint32_t)__bfloat16_as_ushort(h) << 16) | (uint32_t)__bfloat16_as_ushort(lo);
}

#define LDSM4(R, addr) \
    asm volatile("ldmatrix.sync.aligned.m8n8.x4.shared.b16 {%0,%1,%2,%3}, [%4];" \
                 : "=r"((R)[0]), "=r"((R)[1]), "=r"((R)[2]), "=r"((R)[3]) \
                 : "r"(addr))

#define MMA16816(D, Aq, b0, b1) \
    asm volatile("mma.sync.aligned.m16n8k16.row.col.f32.bf16.bf16.f32 " \
                 "{%0,%1,%2,%3}, {%4,%5,%6,%7}, {%8,%9}, {%0,%1,%2,%3};" \
                 : "+f"((D)[0]), "+f"((D)[1]), "+f"((D)[2]), "+f"((D)[3]) \
                 : "r"((Aq)[0]), "r"((Aq)[1]), "r"((Aq)[2]), "r"((Aq)[3]), \
                   "r"(b0), "r"(b1))

// ---------------- embedding ----------------
__global__ __launch_bounds__(256)
void embed_kernel(const int* __restrict__ x,
                  const float4* __restrict__ atom,
                  const float4* __restrict__ chir,
                  const float4* __restrict__ hyb,
                  float4* __restrict__ h) {
    int t = blockIdx.x * blockDim.x + threadIdx.x;
    if (t >= N_NODES * 32) return;
    int node = t >> 5, lane = t & 31;
    int a  = x[3 * node + 0];
    int c  = x[3 * node + 1];
    int hy = x[3 * node + 2];
    float4 o  = atom[a * 32 + lane];
    float4 c4 = chir[c * 32 + lane];
    float4 h4 = hyb[hy * 32 + lane];
    o.x += c4.x + h4.x; o.y += c4.y + h4.y;
    o.z += c4.z + h4.z; o.w += c4.w + h4.w;
    h[t] = o;
}

// ---------------- CSR build ----------------
__global__ __launch_bounds__(256)
void zero_counts(int* __restrict__ counts, float* __restrict__ sums) {
    int t = blockIdx.x * blockDim.x + threadIdx.x;
    if (t < N_NODES) counts[t] = 0;
    if (t < 2 * EMB) sums[t] = 0.f;
}

__global__ __launch_bounds__(256)
void hist_kernel(const int* __restrict__ ei, int* __restrict__ counts) {
    int e = blockIdx.x * blockDim.x + threadIdx.x;
    if (e < N_EDGES) atomicAdd(&counts[ei[N_EDGES + e]], 1);
}

__global__ __launch_bounds__(1024)
void scan_kernel(const int* __restrict__ counts, int* __restrict__ rowptr,
                 int* __restrict__ cursor) {
    __shared__ int part[1024];
    const int tid = threadIdx.x;
    const int CH = (N_NODES + 1023) / 1024;
    const int beg = tid * CH;
    int s = 0;
    for (int i = 0; i < CH; i++) {
        int idx = beg + i;
        if (idx < N_NODES) s += counts[idx];
    }
    part[tid] = s;
    __syncthreads();
    for (int off = 1; off < 1024; off <<= 1) {
        int add = (tid >= off) ? part[tid - off] : 0;
        __syncthreads();
        part[tid] += add;
        __syncthreads();
    }
    int run = (tid > 0) ? part[tid - 1] : 0;
    for (int i = 0; i < CH; i++) {
        int idx = beg + i;
        if (idx < N_NODES) {
            int c = counts[idx];
            rowptr[idx] = run;
            cursor[idx] = run;
            run += c;
        }
    }
    if (tid == 1023) rowptr[N_NODES] = part[1023];
}

__global__ __launch_bounds__(256)
void fill_kernel(const int* __restrict__ ei, const int* __restrict__ ea,
                 int* __restrict__ cursor, unsigned* __restrict__ elist) {
    int e = blockIdx.x * blockDim.x + threadIdx.x;
    if (e >= N_EDGES) return;
    int src = ei[e];
    int dst = ei[N_EDGES + e];
    unsigned a0 = (unsigned)ea[2 * e];
    unsigned a1 = (unsigned)ea[2 * e + 1];
    int pos = atomicAdd(&cursor[dst], 1);
    elist[pos] = (unsigned)src | (a0 << 16) | (a1 << 19);
}

// ---------------- weight transpose + bf16 hi/lo pack (once) ----------------
__global__ __launch_bounds__(256)
void wconv_kernel(const float* __restrict__ W1, const float* __restrict__ W2,
                  uint32_t* __restrict__ w1p, uint32_t* __restrict__ w2p) {
    int i = blockIdx.x * blockDim.x + threadIdx.x;
    const int T1 = NLAYER * 128 * 256;
    if (i < T1) {
        int k = i & 127;
        int n = (i >> 7) & 255;
        int l = i >> 15;
        float v = W1[l * 32768 + k * 256 + n];
        w1p[l * 32768 + n * 128 + k] = packhilo(v);
    } else {
        int j = i - T1;
        if (j < NLAYER * 128 * 256) {
            int k = j & 255;
            int n = (j >> 8) & 127;
            int l = j >> 15;
            float v = W2[l * 32768 + k * 128 + n];
            w2p[l * 32768 + n * 256 + k] = packhilo(v);
        }
    }
}

// ---------------- gather aggregation -> packed hi/lo ----------------
__global__ __launch_bounds__(256)
void agg_pack(const float4* __restrict__ h,
              const int* __restrict__ rowptr,
              const unsigned* __restrict__ elist,
              const float4* __restrict__ e1l,
              const float4* __restrict__ e2l,
              uint4* __restrict__ aggp) {
    __shared__ float4 sEE[24 * 32];
    int tid = threadIdx.x;
    for (int i = tid; i < 24 * 32; i += 256) {
        int combo = i >> 5, lane = i & 31;
        int a0 = combo >> 2, a1 = combo & 3;
        float4 v1 = e1l[a0 * 32 + lane];
        float4 v2 = e2l[a1 * 32 + lane];
        float4 o;
        o.x = v1.x + v2.x; o.y = v1.y + v2.y;
        o.z = v1.z + v2.z; o.w = v1.w + v2.w;
        sEE[i] = o;
    }
    __syncthreads();

    int t = blockIdx.x * blockDim.x + tid;
    int n = t >> 5, lane = t & 31;
    if (n >= N_NODES) return;
    int beg = rowptr[n], end = rowptr[n + 1];
    float4 acc = make_float4(0.f, 0.f, 0.f, 0.f);
    for (int e = beg; e < end; e++) {
        unsigned p = elist[e];
        int src = (int)(p & 0xFFFFu);
        int combo = (int)(((p >> 16) & 7u) * 4u + ((p >> 19) & 3u));
        float4 v  = h[src * 32 + lane];
        float4 ee = sEE[combo * 32 + lane];
        acc.x += v.x + ee.x; acc.y += v.y + ee.y;
        acc.z += v.z + ee.z; acc.w += v.w + ee.w;
    }
    uint4 o;
    o.x = packhilo(acc.x); o.y = packhilo(acc.y);
    o.z = packhilo(acc.z); o.w = packhilo(acc.w);
    aggp[n * 32 + lane] = o;
}

// ---------------- split-bf16 mma.sync GEMM ----------------
// C[M,N] = A[M,K] @ B^T[N,K] + bias.  A, Bp are hi/lo-packed u32.
// D = Ah*Bh + Ah*Bl + Al*Bh (fp32 accum).  Block tile 128x128, BK=32.
// 8 warps: warp (w>>2) in M (64 rows), (w&3) in N (32 cols).
// PACK_OUT: relu + repack hi/lo -> Cp.  STATS: BN col sums -> sums.
template<int K, int N, bool PACK_OUT, bool STATS>
__global__ __launch_bounds__(256)
void gemm_mma(const uint32_t* __restrict__ A, const uint32_t* __restrict__ Bp,
              const float* __restrict__ bias, uint32_t* __restrict__ Cp,
              float* __restrict__ Cf, float* __restrict__ sums, int M) {
    // stride 40 bf16 (80 B): ldmatrix rows map to disjoint 4-bank groups
    __shared__ __align__(16) uint16_t sAh[128][40];
    __shared__ __align__(16) uint16_t sAl[128][40];
    __shared__ __align__(16) uint16_t sBh[128][40];
    __shared__ __align__(16) uint16_t sBl[128][40];
    __shared__ float sS[128], sQ[128];

    const int tid = threadIdx.x;
    const int wid = tid >> 5, lane = tid & 31;
    const int row0 = blockIdx.x * 128;
    const int col0 = blockIdx.y * 128;

    if (STATS && tid < 128) { sS[tid] = 0.f; sQ[tid] = 0.f; }

    float acc[4][4][4];
#pragma unroll
    for (int a = 0; a < 4; a++)
#pragma unroll
        for (int b = 0; b < 4; b++)
#pragma unroll
            for (int c = 0; c < 4; c++) acc[a][b][c] = 0.f;

    const uint32_t aAh = (uint32_t)__cvta_generic_to_shared(&sAh[0][0]);
    const uint32_t aAl = (uint32_t)__cvta_generic_to_shared(&sAl[0][0]);
    const uint32_t aBh = (uint32_t)__cvta_generic_to_shared(&sBh[0][0]);
    const uint32_t aBl = (uint32_t)__cvta_generic_to_shared(&sBl[0][0]);

    const int m0w = (wid >> 2) * 64;
    const int n0w = (wid & 3) * 32;
    const int rsel = lane & 15;
    const int kqsel = (lane >> 4) * 8;   // +8 k for upper 16 lanes

    for (int kc = 0; kc < K / 32; kc++) {
        __syncthreads();
        // ---- load + unpack A chunk: 128 rows x 32 packed cols ----
#pragma unroll
        for (int i = 0; i < 4; i++) {
            int idx = tid + i * 256;     // 0..1023
            int r = idx >> 3;
            int c4 = (idx & 7) * 4;      // first of 4 u32 cols
            uint4 p = make_uint4(0u, 0u, 0u, 0u);
            if (row0 + r < M)
                p = *(const uint4*)(A + (size_t)(row0 + r) * K + kc * 32 + c4);
            uint32_t h0, h1, l0, l1;
            asm("prmt.b32 %0,%1,%2,0x7632;" : "=r"(h0) : "r"(p.x), "r"(p.y));
            asm("prmt.b32 %0,%1,%2,0x7632;" : "=r"(h1) : "r"(p.z), "r"(p.w));
            asm("prmt.b32 %0,%1,%2,0x5410;" : "=r"(l0) : "r"(p.x), "r"(p.y));
            asm("prmt.b32 %0,%1,%2,0x5410;" : "=r"(l1) : "r"(p.z), "r"(p.w));
            *(uint2*)&sAh[r][c4] = make_uint2(h0, h1);
            *(uint2*)&sAl[r][c4] = make_uint2(l0, l1);
        }
        // ---- load + unpack B chunk: 128 n-rows x 32 packed cols ----
#pragma unroll
        for (int i = 0; i < 4; i++) {
            int idx = tid + i * 256;
            int r = idx >> 3;
            int c4 = (idx & 7) * 4;
            uint4 p = *(const uint4*)(Bp + (size_t)(col0 + r) * K + kc * 32 + c4);
            uint32_t h0, h1, l0, l1;
            asm("prmt.b32 %0,%1,%2,0x7632;" : "=r"(h0) : "r"(p.x), "r"(p.y));
            asm("prmt.b32 %0,%1,%2,0x7632;" : "=r"(h1) : "r"(p.z), "r"(p.w));
            asm("prmt.b32 %0,%1,%2,0x5410;" : "=r"(l0) : "r"(p.x), "r"(p.y));
            asm("prmt.b32 %0,%1,%2,0x5410;" : "=r"(l1) : "r"(p.z), "r"(p.w));
            *(uint2*)&sBh[r][c4] = make_uint2(h0, h1);
            *(uint2*)&sBl[r][c4] = make_uint2(l0, l1);
        }
        __syncthreads();

        // ---- compute: 2 k-steps of 16 ----
#pragma unroll
        for (int ks = 0; ks < 2; ks++) {
            const int kof = (ks * 16 + kqsel) * 2;   // byte offset in row
            uint32_t Ah[4][4], Al[4][4], Bh[2][4], Bl[2][4];
#pragma unroll
            for (int tm = 0; tm < 4; tm++) {
                uint32_t rowb = (uint32_t)(m0w + tm * 16 + rsel) * 80u + kof;
                LDSM4(Ah[tm], aAh + rowb);
                LDSM4(Al[tm], aAl + rowb);
            }
#pragma unroll
            for (int tg = 0; tg < 2; tg++) {
                uint32_t rowb = (uint32_t)(n0w + tg * 16 + rsel) * 80u + kof;
                LDSM4(Bh[tg], aBh + rowb);
                LDSM4(Bl[tg], aBl + rowb);
            }
#pragma unroll
            for (int tm = 0; tm < 4; tm++)
#pragma unroll
                for (int tn = 0; tn < 4; tn++) {
                    const int tg = tn >> 1, hf = tn & 1;
                    MMA16816(acc[tm][tn], Ah[tm], Bh[tg][hf], Bh[tg][2 + hf]);
                    MMA16816(acc[tm][tn], Ah[tm], Bl[tg][hf], Bl[tg][2 + hf]);
                    MMA16816(acc[tm][tn], Al[tm], Bh[tg][hf], Bh[tg][2 + hf]);
                }
        }
    }

    // ---- epilogue ----
#pragma unroll
    for (int tn = 0; tn < 4; tn++) {
        const int cl = n0w + tn * 8 + 2 * (lane & 3);
        const float b0v = bias[col0 + cl];
        const float b1v = bias[col0 + cl + 1];
        float cs0 = 0.f, cq0 = 0.f, cs1 = 0.f, cq1 = 0.f;
#pragma unroll
        for (int tm = 0; tm < 4; tm++) {
#pragma unroll
            for (int hr = 0; hr < 2; hr++) {
                int r = row0 + m0w + tm * 16 + (lane >> 2) + hr * 8;
                float v0 = acc[tm][tn][hr * 2 + 0] + b0v;
                float v1 = acc[tm][tn][hr * 2 + 1] + b1v;
                if (r < M) {
                    if (PACK_OUT) {
                        uint2 pk = make_uint2(packhilo(fmaxf(v0, 0.f)),
                                              packhilo(fmaxf(v1, 0.f)));
                        *(uint2*)(Cp + (size_t)r * N + col0 + cl) = pk;
                    } else {
                        *(float2*)(Cf + (size_t)r * N + col0 + cl) = make_float2(v0, v1);
                    }
                    if (STATS) {
                        cs0 += v0; cq0 += v0 * v0;
                        cs1 += v1; cq1 += v1 * v1;
                    }
                }
            }
        }
        if (STATS) {
            atomicAdd(&sS[cl],     cs0);
            atomicAdd(&sQ[cl],     cq0);
            atomicAdd(&sS[cl + 1], cs1);
            atomicAdd(&sQ[cl + 1], cq1);
        }
    }
    if (STATS) {
        __syncthreads();
        if (tid < 128) {
            atomicAdd(&sums[tid],       sS[tid]);
            atomicAdd(&sums[EMB + tid], sQ[tid]);
        }
    }
}

// ---------------- BN ----------------
__global__ void bn_prep(float* __restrict__ sums,
                        const float* __restrict__ gamma,
                        const float* __restrict__ beta,
                        float* __restrict__ scale,
                        float* __restrict__ shift) {
    int c = threadIdx.x;
    if (c >= EMB) return;
    const float inv_n = 1.0f / (float)N_NODES;
    float mu  = sums[c] * inv_n;
    float var = sums[EMB + c] * inv_n - mu * mu;
    float rs  = rsqrtf(var + BN_EPS);
    float sc  = gamma[c] * rs;
    scale[c] = sc;
    shift[c] = beta[c] - mu * sc;
    sums[c] = 0.f;
    sums[EMB + c] = 0.f;
}

__global__ __launch_bounds__(256)
void bn_apply(const float4* __restrict__ h2, float4* __restrict__ out,
              const float4* __restrict__ scale, const float4* __restrict__ shift,
              int relu) {
    int t = blockIdx.x * blockDim.x + threadIdx.x;
    if (t >= N_NODES * 32) return;
    int lane = t & 31;
    float4 v  = h2[t];
    float4 sc = scale[lane];
    float4 sh = shift[lane];
    float4 o;
    o.x = fmaf(v.x, sc.x, sh.x);
    o.y = fmaf(v.y, sc.y, sh.y);
    o.z = fmaf(v.z, sc.z, sh.z);
    o.w = fmaf(v.w, sc.w, sh.w);
    if (relu) {
        o.x = fmaxf(o.x, 0.f); o.y = fmaxf(o.y, 0.f);
        o.z = fmaxf(o.z, 0.f); o.w = fmaxf(o.w, 0.f);
    }
    out[t] = o;
}

// ---------------- launch ----------------
extern "C" void kernel_launch(void* const* d_in, const int* in_sizes, int n_in,
                              void* d_out, int out_size) {
    const int*   x    = (const int*)  d_in[0];
    const int*   ei   = (const int*)  d_in[1];
    const int*   ea   = (const int*)  d_in[2];
    const float* atom = (const float*)d_in[3];
    const float* chir = (const float*)d_in[4];
    const float* hyb  = (const float*)d_in[5];
    const float* e1   = (const float*)d_in[6];
    const float* e2   = (const float*)d_in[7];
    const float* W1   = (const float*)d_in[8];
    const float* b1   = (const float*)d_in[9];
    const float* W2   = (const float*)d_in[10];
    const float* b2   = (const float*)d_in[11];
    const float* gamma= (const float*)d_in[12];
    const float* beta = (const float*)d_in[13];
    float* out = (float*)d_out;

    float *h, *h2, *sums, *scale, *shift;
    uint32_t *aggp, *hiddenp, *w1p, *w2p;
    int *counts, *cursor, *rowptr;
    unsigned* elist;
    cudaGetSymbolAddress((void**)&h,       g_h);
    cudaGetSymbolAddress((void**)&aggp,    g_aggp);
    cudaGetSymbolAddress((void**)&hiddenp, g_hiddenp);
    cudaGetSymbolAddress((void**)&h2,      g_h2);
    cudaGetSymbolAddress((void**)&sums,    g_sums);
    cudaGetSymbolAddress((void**)&scale,   g_scale);
    cudaGetSymbolAddress((void**)&shift,   g_shift);
    cudaGetSymbolAddress((void**)&counts,  g_counts);
    cudaGetSymbolAddress((void**)&cursor,  g_cursor);
    cudaGetSymbolAddress((void**)&rowptr,  g_rowptr);
    cudaGetSymbolAddress((void**)&elist,   g_elist);
    cudaGetSymbolAddress((void**)&w1p,     g_w1p);
    cudaGetSymbolAddress((void**)&w2p,     g_w2p);

    const int tpb = 256;
    const int node_grid = (N_NODES * 32) / tpb;
    const int edge_grid = (N_EDGES + tpb - 1) / tpb;
    const int cnt_grid  = (N_NODES + tpb - 1) / tpb;
    const int tile_grid = (N_NODES + 127) / 128;       // 391
    const dim3 g1(tile_grid, 2);                       // GEMM1: N=256
    const dim3 g2(tile_grid, 1);                       // GEMM2: N=128

    zero_counts<<<cnt_grid, tpb>>>(counts, sums);
    hist_kernel<<<edge_grid, tpb>>>(ei, counts);
    scan_kernel<<<1, 1024>>>(counts, rowptr, cursor);
    fill_kernel<<<edge_grid, tpb>>>(ei, ea, cursor, elist);
    embed_kernel<<<node_grid, tpb>>>(x, (const float4*)atom, (const float4*)chir,
                                     (const float4*)hyb, (float4*)h);
    wconv_kernel<<<(2 * NLAYER * 32768 + tpb - 1) / tpb, tpb>>>(W1, W2, w1p, w2p);

    for (int l = 0; l < NLAYER; l++) {
        const float4* e1l = (const float4*)(e1 + (size_t)l * 6 * EMB);
        const float4* e2l = (const float4*)(e2 + (size_t)l * 4 * EMB);
        agg_pack<<<node_grid, tpb>>>((const float4*)h, rowptr, elist, e1l, e2l,
                                     (uint4*)aggp);
        gemm_mma<128, 256, true, false><<<g1, tpb>>>(
            aggp, w1p + (size_t)l * 32768, b1 + (size_t)l * 256,
            hiddenp, nullptr, nullptr, N_NODES);
        gemm_mma<256, 128, false, true><<<g2, tpb>>>(
            hiddenp, w2p + (size_t)l * 32768, b2 + (size_t)l * 128,
            nullptr, h2, sums, N_NODES);
        bn_prep<<<1, 128>>>(sums, gamma + (size_t)l * EMB, beta + (size_t)l * EMB,
                            scale, shift);
        bn_apply<<<node_grid, tpb>>>((const float4*)h2,
                                     (l == NLAYER - 1) ? (float4*)out : (float4*)h,
                                     (const float4*)scale, (const float4*)shift,
                                     (l < NLAYER - 1) ? 1 : 0);
    }
}